// round 2
// baseline (speedup 1.0000x reference)
#include <cuda_runtime.h>

// ---------------------------------------------------------------------------
// AdaptiveDCA: qkv GEMM -> 4x dilated 3x3 attention -> gated concat
// Shapes: x (8,512,64,64), w_qkv (1536,512), w_gate (4,512), b_gate (4)
// out (8,512,64,64) fp32
// ---------------------------------------------------------------------------

#define B_   8
#define C_   512
#define HW_  4096        // 64*64
#define M_   1536        // 3*512
#define K_   512

// Scratch (device globals: allocation-free per harness rules)
__device__ float g_qkv[(size_t)B_ * M_ * HW_];   // ~201 MB
__device__ float g_pooled[B_ * C_];
__device__ float g_gate[B_ * 4];

// ---------------------------------------------------------------------------
// GEMM: qkv[b,o,n] = sum_c w[o,c] * x[b,c,n]
// Classic 128x128x8 SGEMM, 8x8 register tile, 256 threads.
// ---------------------------------------------------------------------------
__global__ __launch_bounds__(256) void gemm_qkv_kernel(
    const float* __restrict__ W, const float* __restrict__ X)
{
    constexpr int BM = 128, BN = 128, BK = 8, TM = 8, TN = 8;
    __shared__ float As[BK][BM];   // A tile, transposed (k-major)
    __shared__ float Bs[BK][BN];

    const int tid = threadIdx.x;
    const int bz  = blockIdx.z;    // batch

    const float* A = W + (size_t)blockIdx.y * BM * K_;              // [BM x K] ld=K
    const float* Bm = X + (size_t)bz * C_ * HW_ + blockIdx.x * BN;  // [K x BN] ld=HW
    float* Cm = g_qkv + ((size_t)bz * M_ + blockIdx.y * BM) * HW_ + blockIdx.x * BN;

    const int a_row = tid >> 1;          // 0..127
    const int a_col = (tid & 1) * 4;     // 0 or 4
    const int b_row = tid >> 5;          // 0..7
    const int b_col = (tid & 31) * 4;    // 0..124
    const int ty = tid >> 4;             // 0..15
    const int tx = tid & 15;             // 0..15

    float acc[TM][TN] = {};

    for (int k0 = 0; k0 < K_; k0 += BK) {
        float4 av = *(const float4*)(A + (size_t)a_row * K_ + k0 + a_col);
        As[a_col + 0][a_row] = av.x;
        As[a_col + 1][a_row] = av.y;
        As[a_col + 2][a_row] = av.z;
        As[a_col + 3][a_row] = av.w;
        *(float4*)&Bs[b_row][b_col] =
            *(const float4*)(Bm + (size_t)(k0 + b_row) * HW_ + b_col);
        __syncthreads();

        #pragma unroll
        for (int k = 0; k < BK; k++) {
            float a_frag[TM], b_frag[TN];
            *(float4*)&a_frag[0] = *(const float4*)&As[k][ty * TM];
            *(float4*)&a_frag[4] = *(const float4*)&As[k][ty * TM + 4];
            *(float4*)&b_frag[0] = *(const float4*)&Bs[k][tx * TN];
            *(float4*)&b_frag[4] = *(const float4*)&Bs[k][tx * TN + 4];
            #pragma unroll
            for (int m = 0; m < TM; m++)
                #pragma unroll
                for (int n = 0; n < TN; n++)
                    acc[m][n] += a_frag[m] * b_frag[n];
        }
        __syncthreads();
    }

    #pragma unroll
    for (int m = 0; m < TM; m++) {
        #pragma unroll
        for (int n = 0; n < TN; n += 4) {
            float4 v = make_float4(acc[m][n], acc[m][n+1], acc[m][n+2], acc[m][n+3]);
            *(float4*)(Cm + (size_t)(ty * TM + m) * HW_ + tx * TN + n) = v;
        }
    }
}

// ---------------------------------------------------------------------------
// Global average pool: pooled[b,c] = mean_n x[b,c,n]
// One block per (b,c), 256 threads reduce 4096 elements.
// ---------------------------------------------------------------------------
__global__ __launch_bounds__(256) void pool_kernel(const float* __restrict__ X)
{
    const int bc = blockIdx.x;  // 0..4095
    const float* xp = X + (size_t)bc * HW_;
    float sum = 0.f;
    for (int i = threadIdx.x; i < HW_; i += 256) sum += xp[i];

    // warp reduce
    #pragma unroll
    for (int o = 16; o > 0; o >>= 1) sum += __shfl_xor_sync(0xFFFFFFFFu, sum, o);

    __shared__ float sm[8];
    if ((threadIdx.x & 31) == 0) sm[threadIdx.x >> 5] = sum;
    __syncthreads();
    if (threadIdx.x == 0) {
        float t = 0.f;
        #pragma unroll
        for (int i = 0; i < 8; i++) t += sm[i];
        g_pooled[bc] = t * (1.0f / HW_);
    }
}

// ---------------------------------------------------------------------------
// Gate: logits[b,i] = pooled[b,:] . w_gate[i,:] + b_gate[i]; softmax over i.
// 32 threads: thread t -> (b = t/4, i = t%4).
// ---------------------------------------------------------------------------
__global__ void gate_kernel(const float* __restrict__ Wg, const float* __restrict__ bg)
{
    __shared__ float lg[32];
    const int t = threadIdx.x;
    const int b = t >> 2, i = t & 3;
    float dot = bg[i];
    const float* p = g_pooled + b * C_;
    const float* w = Wg + i * C_;
    for (int c = 0; c < C_; c++) dot += p[c] * w[c];
    lg[t] = dot;
    __syncthreads();
    if (t < B_) {
        float l0 = lg[t*4+0], l1 = lg[t*4+1], l2 = lg[t*4+2], l3 = lg[t*4+3];
        float m = fmaxf(fmaxf(l0, l1), fmaxf(l2, l3));
        float e0 = expf(l0 - m), e1 = expf(l1 - m), e2 = expf(l2 - m), e3 = expf(l3 - m);
        float inv = 1.0f / (e0 + e1 + e2 + e3);
        g_gate[t*4+0] = e0 * inv;
        g_gate[t*4+1] = e1 * inv;
        g_gate[t*4+2] = e2 * inv;
        g_gate[t*4+3] = e3 * inv;
    }
}

// ---------------------------------------------------------------------------
// Dilated 3x3 attention + gate + write out.
// One thread per position n, per (b, dilation i, head).
// Zero-padding semantics: OOB neighbor -> logit 0 (included in softmax), v=0.
// Phase 1 (uses q[64]) computes the 9 softmax weights; q is dead before the
// v pass so the register allocator can overlap q[] with acc[].
// ---------------------------------------------------------------------------
__global__ __launch_bounds__(256) void attn_kernel(float* __restrict__ out)
{
    const int n = blockIdx.x * 256 + threadIdx.x;   // 0..4095
    const int dh = blockIdx.y;                       // 0..7
    const int b  = blockIdx.z;
    const int i    = dh >> 1;       // dilation index
    const int head = dh & 1;
    const int dil  = 1 << i;        // 1,2,4,8
    const int h = n >> 6, w = n & 63;
    const float scale = 0.125f;     // 64^-0.5

    const size_t base = ((size_t)b * M_ + i * 128 + head * 64) * HW_;
    const float* qp = g_qkv + base;                        // q slab
    const float* kp = g_qkv + base + (size_t)C_ * HW_;     // k slab (+512 ch)
    const float* vp = g_qkv + base + (size_t)2 * C_ * HW_; // v slab (+1024 ch)

    float s[9];
    int   nn[9];
    bool  ok[9];

    // ---- Phase 1: logits (q live only here) ----
    {
        float q[64];
        #pragma unroll
        for (int c = 0; c < 64; c++) q[c] = qp[(size_t)c * HW_ + n];

        #pragma unroll
        for (int j = 0; j < 9; j++) {
            const int dy = (j / 3 - 1) * dil;
            const int dx = (j % 3 - 1) * dil;
            const int hh = h + dy, ww = w + dx;
            const bool v_ok = ((unsigned)hh < 64u) && ((unsigned)ww < 64u);
            const int nnj = hh * 64 + ww;
            nn[j] = nnj; ok[j] = v_ok;
            float dot = 0.f;
            if (v_ok) {
                const float* kk = kp + nnj;
                #pragma unroll
                for (int c = 0; c < 64; c++) dot += q[c] * kk[(size_t)c * HW_];
            }
            s[j] = dot * scale;   // OOB -> exactly 0, still enters softmax
        }
    }

    // ---- softmax over 9 ----
    float m = s[0];
    #pragma unroll
    for (int j = 1; j < 9; j++) m = fmaxf(m, s[j]);
    float sum = 0.f;
    #pragma unroll
    for (int j = 0; j < 9; j++) { s[j] = expf(s[j] - m); sum += s[j]; }
    const float inv = 1.0f / sum;
    #pragma unroll
    for (int j = 0; j < 9; j++) s[j] *= inv;

    // ---- Phase 2: weighted v accumulation ----
    float acc[64];
    #pragma unroll
    for (int c = 0; c < 64; c++) acc[c] = 0.f;
    #pragma unroll
    for (int j = 0; j < 9; j++) {
        if (ok[j]) {
            const float p = s[j];
            const float* vv = vp + nn[j];
            #pragma unroll
            for (int c = 0; c < 64; c++) acc[c] += p * vv[(size_t)c * HW_];
        }
    }

    const float g = g_gate[b * 4 + i];
    float* op = out + ((size_t)b * C_ + i * 128 + head * 64) * HW_ + n;
    #pragma unroll
    for (int c = 0; c < 64; c++) op[(size_t)c * HW_] = g * acc[c];
}

// ---------------------------------------------------------------------------
extern "C" void kernel_launch(void* const* d_in, const int* in_sizes, int n_in,
                              void* d_out, int out_size)
{
    const float* x      = (const float*)d_in[0];
    const float* w_qkv  = (const float*)d_in[1];
    const float* w_gate = (const float*)d_in[2];
    const float* b_gate = (const float*)d_in[3];
    float* out = (float*)d_out;

    // qkv = W @ x  (per batch)
    gemm_qkv_kernel<<<dim3(HW_ / 128, M_ / 128, B_), 256>>>(w_qkv, x);

    // gate path (independent of GEMM)
    pool_kernel<<<B_ * C_, 256>>>(x);
    gate_kernel<<<1, 32>>>(w_gate, b_gate);

    // attention + gating + output
    attn_kernel<<<dim3(HW_ / 256, 8, B_), 256>>>(out);
}

// round 4
// speedup vs baseline: 1.7733x; 1.7733x over previous
#include <cuda_runtime.h>
#include <cstdint>

// ---------------------------------------------------------------------------
// AdaptiveDCA: qkv GEMM (TF32 tensor cores) -> 4x dilated 3x3 attention -> gate
// x (8,512,64,64), w_qkv (1536,512), w_gate (4,512), b_gate (4) -> out fp32
// ---------------------------------------------------------------------------

#define B_   8
#define C_   512
#define HW_  4096
#define M_   1536
#define K_   512

__device__ float g_qkv[(size_t)B_ * M_ * HW_];
__device__ float g_pooled[B_ * C_];
__device__ float g_gate[B_ * 4];

__device__ __forceinline__ uint32_t f2tf32(float x) {
    uint32_t r;
    asm("cvt.rna.tf32.f32 %0, %1;" : "=r"(r) : "f"(x));
    return r;
}

__device__ __forceinline__ void mma_tf32(
    float& c0, float& c1, float& c2, float& c3,
    uint32_t a0, uint32_t a1, uint32_t a2, uint32_t a3,
    uint32_t b0, uint32_t b1)
{
    asm volatile(
        "mma.sync.aligned.m16n8k8.row.col.f32.tf32.tf32.f32 "
        "{%0,%1,%2,%3}, {%4,%5,%6,%7}, {%8,%9}, {%0,%1,%2,%3};"
        : "+f"(c0), "+f"(c1), "+f"(c2), "+f"(c3)
        : "r"(a0), "r"(a1), "r"(a2), "r"(a3), "r"(b0), "r"(b1));
}

// ---------------------------------------------------------------------------
// TF32 GEMM: qkv[b,o,n] = sum_c W[o,c] * X[b,c,n]
// BM=128, BN=128, BK=16. 8 warps: warp grid 2(m) x 4(n), warp tile 64x32.
// m16n8k8 -> 4 m-tiles x 4 n-tiles per warp per k8-step.
// ---------------------------------------------------------------------------
#define BK_ 16
#define LDA_ 136   // padded row length (bank-conflict-free fragment loads)

__global__ __launch_bounds__(256) void gemm_qkv_tc(
    const float* __restrict__ W, const float* __restrict__ X)
{
    __shared__ uint32_t As[BK_][LDA_];   // [k][m], tf32 bits
    __shared__ uint32_t Bs[BK_][LDA_];   // [k][n], tf32 bits

    const int tid = threadIdx.x;
    const int bz  = blockIdx.z;
    const int bm0 = blockIdx.y * 128;
    const int bn0 = blockIdx.x * 128;

    const float* Ag = W + (size_t)bm0 * K_;
    const float* Bg = X + (size_t)bz * C_ * HW_ + bn0;
    float* Cg = g_qkv + ((size_t)bz * M_ + bm0) * HW_ + bn0;

    // global-load mapping
    const int a_m  = tid & 127;          // 0..127
    const int a_kg = (tid >> 7) * 8;     // 0 or 8
    const int b_k  = tid >> 5;           // 0..7
    const int b_n  = (tid & 31) * 4;     // 0..124

    // warp mapping
    const int wid    = tid >> 5;
    const int lane   = tid & 31;
    const int warp_m = (wid & 1) * 64;
    const int warp_n = (wid >> 1) * 32;
    const int lr = lane >> 2;            // 0..7
    const int lc = lane & 3;             // 0..3

    float acc[4][4][4];
    #pragma unroll
    for (int mt = 0; mt < 4; mt++)
        #pragma unroll
        for (int nt = 0; nt < 4; nt++)
            #pragma unroll
            for (int r = 0; r < 4; r++) acc[mt][nt][r] = 0.f;

    // prefetch tile 0
    float4 pa0 = *(const float4*)(Ag + (size_t)a_m * K_ + a_kg);
    float4 pa1 = *(const float4*)(Ag + (size_t)a_m * K_ + a_kg + 4);
    float4 pb0 = *(const float4*)(Bg + (size_t)b_k * HW_ + b_n);
    float4 pb1 = *(const float4*)(Bg + (size_t)(b_k + 8) * HW_ + b_n);

    const int NITER = K_ / BK_;   // 32
    for (int iter = 0; iter < NITER; iter++) {
        // stage current tile into smem (tf32 convert; vector STS for B)
        As[a_kg + 0][a_m] = f2tf32(pa0.x);
        As[a_kg + 1][a_m] = f2tf32(pa0.y);
        As[a_kg + 2][a_m] = f2tf32(pa0.z);
        As[a_kg + 3][a_m] = f2tf32(pa0.w);
        As[a_kg + 4][a_m] = f2tf32(pa1.x);
        As[a_kg + 5][a_m] = f2tf32(pa1.y);
        As[a_kg + 6][a_m] = f2tf32(pa1.z);
        As[a_kg + 7][a_m] = f2tf32(pa1.w);
        {
            uint4 v0 = make_uint4(f2tf32(pb0.x), f2tf32(pb0.y),
                                  f2tf32(pb0.z), f2tf32(pb0.w));
            uint4 v1 = make_uint4(f2tf32(pb1.x), f2tf32(pb1.y),
                                  f2tf32(pb1.z), f2tf32(pb1.w));
            *(uint4*)&Bs[b_k][b_n]     = v0;
            *(uint4*)&Bs[b_k + 8][b_n] = v1;
        }
        __syncthreads();

        // prefetch next tile (LDGs overlap with MMA below)
        if (iter + 1 < NITER) {
            const int k0 = (iter + 1) * BK_;
            pa0 = *(const float4*)(Ag + (size_t)a_m * K_ + k0 + a_kg);
            pa1 = *(const float4*)(Ag + (size_t)a_m * K_ + k0 + a_kg + 4);
            pb0 = *(const float4*)(Bg + (size_t)(k0 + b_k) * HW_ + b_n);
            pb1 = *(const float4*)(Bg + (size_t)(k0 + b_k + 8) * HW_ + b_n);
        }

        // two k8 steps
        #pragma unroll
        for (int s = 0; s < 2; s++) {
            const int ks = s * 8;
            uint32_t af[4][4], bf[4][2];
            #pragma unroll
            for (int mt = 0; mt < 4; mt++) {
                const int mbase = warp_m + mt * 16 + lr;
                af[mt][0] = As[ks + lc    ][mbase    ];
                af[mt][1] = As[ks + lc    ][mbase + 8];
                af[mt][2] = As[ks + lc + 4][mbase    ];
                af[mt][3] = As[ks + lc + 4][mbase + 8];
            }
            #pragma unroll
            for (int nt = 0; nt < 4; nt++) {
                const int nbase = warp_n + nt * 8 + lr;
                bf[nt][0] = Bs[ks + lc    ][nbase];
                bf[nt][1] = Bs[ks + lc + 4][nbase];
            }
            #pragma unroll
            for (int mt = 0; mt < 4; mt++)
                #pragma unroll
                for (int nt = 0; nt < 4; nt++)
                    mma_tf32(acc[mt][nt][0], acc[mt][nt][1],
                             acc[mt][nt][2], acc[mt][nt][3],
                             af[mt][0], af[mt][1], af[mt][2], af[mt][3],
                             bf[nt][0], bf[nt][1]);
        }
        __syncthreads();
    }

    // epilogue: C layout c0/c1 at (row, 2*lc), c2/c3 at (row+8, 2*lc)
    #pragma unroll
    for (int mt = 0; mt < 4; mt++) {
        const int r0 = warp_m + mt * 16 + lr;
        #pragma unroll
        for (int nt = 0; nt < 4; nt++) {
            const int cbase = warp_n + nt * 8 + 2 * lc;
            float2 v01 = make_float2(acc[mt][nt][0], acc[mt][nt][1]);
            float2 v23 = make_float2(acc[mt][nt][2], acc[mt][nt][3]);
            *(float2*)(Cg + (size_t)r0 * HW_ + cbase)       = v01;
            *(float2*)(Cg + (size_t)(r0 + 8) * HW_ + cbase) = v23;
        }
    }
}

// ---------------------------------------------------------------------------
// Global average pool
// ---------------------------------------------------------------------------
__global__ __launch_bounds__(256) void pool_kernel(const float* __restrict__ X)
{
    const int bc = blockIdx.x;
    const float* xp = X + (size_t)bc * HW_;
    float sum = 0.f;
    for (int i = threadIdx.x; i < HW_; i += 256) sum += xp[i];
    #pragma unroll
    for (int o = 16; o > 0; o >>= 1) sum += __shfl_xor_sync(0xFFFFFFFFu, sum, o);
    __shared__ float sm[8];
    if ((threadIdx.x & 31) == 0) sm[threadIdx.x >> 5] = sum;
    __syncthreads();
    if (threadIdx.x == 0) {
        float t = 0.f;
        #pragma unroll
        for (int i = 0; i < 8; i++) t += sm[i];
        g_pooled[bc] = t * (1.0f / HW_);
    }
}

// ---------------------------------------------------------------------------
// Gate softmax
// ---------------------------------------------------------------------------
__global__ void gate_kernel(const float* __restrict__ Wg, const float* __restrict__ bg)
{
    __shared__ float lg[32];
    const int t = threadIdx.x;
    const int b = t >> 2, i = t & 3;
    float dot = bg[i];
    const float* p = g_pooled + b * C_;
    const float* w = Wg + i * C_;
    for (int c = 0; c < C_; c++) dot += p[c] * w[c];
    lg[t] = dot;
    __syncthreads();
    if (t < B_) {
        float l0 = lg[t*4+0], l1 = lg[t*4+1], l2 = lg[t*4+2], l3 = lg[t*4+3];
        float m = fmaxf(fmaxf(l0, l1), fmaxf(l2, l3));
        float e0 = expf(l0 - m), e1 = expf(l1 - m), e2 = expf(l2 - m), e3 = expf(l3 - m);
        float inv = 1.0f / (e0 + e1 + e2 + e3);
        g_gate[t*4+0] = e0 * inv;
        g_gate[t*4+1] = e1 * inv;
        g_gate[t*4+2] = e2 * inv;
        g_gate[t*4+3] = e3 * inv;
    }
}

// ---------------------------------------------------------------------------
// Dilated 3x3 attention + gate + write out (zero-padding softmax semantics)
// ---------------------------------------------------------------------------
__global__ __launch_bounds__(256) void attn_kernel(float* __restrict__ out)
{
    const int n = blockIdx.x * 256 + threadIdx.x;
    const int dh = blockIdx.y;
    const int b  = blockIdx.z;
    const int i    = dh >> 1;
    const int head = dh & 1;
    const int dil  = 1 << i;
    const int h = n >> 6, w = n & 63;
    const float scale = 0.125f;

    const size_t base = ((size_t)b * M_ + i * 128 + head * 64) * HW_;
    const float* qp = g_qkv + base;
    const float* kp = g_qkv + base + (size_t)C_ * HW_;
    const float* vp = g_qkv + base + (size_t)2 * C_ * HW_;

    float s[9];
    int   nn[9];
    bool  ok[9];

    {
        float q[64];
        #pragma unroll
        for (int c = 0; c < 64; c++) q[c] = qp[(size_t)c * HW_ + n];

        #pragma unroll
        for (int j = 0; j < 9; j++) {
            const int dy = (j / 3 - 1) * dil;
            const int dx = (j % 3 - 1) * dil;
            const int hh = h + dy, ww = w + dx;
            const bool v_ok = ((unsigned)hh < 64u) && ((unsigned)ww < 64u);
            const int nnj = hh * 64 + ww;
            nn[j] = nnj; ok[j] = v_ok;
            float dot = 0.f;
            if (v_ok) {
                const float* kk = kp + nnj;
                #pragma unroll
                for (int c = 0; c < 64; c++) dot += q[c] * kk[(size_t)c * HW_];
            }
            s[j] = dot * scale;
        }
    }

    float m = s[0];
    #pragma unroll
    for (int j = 1; j < 9; j++) m = fmaxf(m, s[j]);
    float sum = 0.f;
    #pragma unroll
    for (int j = 0; j < 9; j++) { s[j] = expf(s[j] - m); sum += s[j]; }
    const float inv = 1.0f / sum;
    #pragma unroll
    for (int j = 0; j < 9; j++) s[j] *= inv;

    float acc[64];
    #pragma unroll
    for (int c = 0; c < 64; c++) acc[c] = 0.f;
    #pragma unroll
    for (int j = 0; j < 9; j++) {
        if (ok[j]) {
            const float p = s[j];
            const float* vv = vp + nn[j];
            #pragma unroll
            for (int c = 0; c < 64; c++) acc[c] += p * vv[(size_t)c * HW_];
        }
    }

    const float g = g_gate[b * 4 + i];
    float* op = out + ((size_t)b * C_ + i * 128 + head * 64) * HW_ + n;
    #pragma unroll
    for (int c = 0; c < 64; c++) op[(size_t)c * HW_] = g * acc[c];
}

// ---------------------------------------------------------------------------
extern "C" void kernel_launch(void* const* d_in, const int* in_sizes, int n_in,
                              void* d_out, int out_size)
{
    const float* x      = (const float*)d_in[0];
    const float* w_qkv  = (const float*)d_in[1];
    const float* w_gate = (const float*)d_in[2];
    const float* b_gate = (const float*)d_in[3];
    float* out = (float*)d_out;

    gemm_qkv_tc<<<dim3(HW_ / 128, M_ / 128, B_), 256>>>(w_qkv, x);

    pool_kernel<<<B_ * C_, 256>>>(x);
    gate_kernel<<<1, 32>>>(w_gate, b_gate);

    attn_kernel<<<dim3(HW_ / 256, 8, B_), 256>>>(out);
}

// round 8
// speedup vs baseline: 2.2342x; 1.2599x over previous
#include <cuda_runtime.h>
#include <cstdint>

// ---------------------------------------------------------------------------
// AdaptiveDCA: pre-round -> qkv GEMM (mma.sync tf32 + cp.async) -> attention
// x (8,512,64,64), w_qkv (1536,512), w_gate (4,512), b_gate (4) -> out fp32
// NOTE: harness builds at compute_100 (no 'a') -> tcgen05 unavailable; legacy
// mma.sync.m16n8k8.tf32 is the tensor path. No host API calls in
// kernel_launch: kernels reference __device__ globals directly.
// ---------------------------------------------------------------------------

#define B_   8
#define C_   512
#define HW_  4096
#define M_   1536
#define K_   512

__device__ float g_qkv[(size_t)B_ * M_ * HW_];     // ~201 MB scratch
__device__ float g_xtf[(size_t)B_ * C_ * HW_];     // tf32-rounded X (67 MB)
__device__ float g_wtf[(size_t)M_ * K_];           // tf32-rounded W (3 MB)
__device__ float g_pooled[B_ * C_];
__device__ float g_gate[B_ * 4];

__device__ __forceinline__ uint32_t f2tf32(float x) {
    uint32_t r;
    asm("cvt.rna.tf32.f32 %0, %1;" : "=r"(r) : "f"(x));
    return r;
}
__device__ __forceinline__ uint32_t smem_u32(const void* p) {
    uint32_t a;
    asm("{ .reg .u64 t; cvta.to.shared.u64 t, %1; cvt.u32.u64 %0, t; }"
        : "=r"(a) : "l"(p));
    return a;
}

#define CP_ASYNC16(dst, src) \
    asm volatile("cp.async.cg.shared.global [%0], [%1], 16;" \
                 :: "r"(dst), "l"(src) : "memory")
#define CP_COMMIT() asm volatile("cp.async.commit_group;" ::: "memory")
#define CP_WAIT1()  asm volatile("cp.async.wait_group 1;" ::: "memory")

__device__ __forceinline__ void mma_tf32(
    float& c0, float& c1, float& c2, float& c3,
    uint32_t a0, uint32_t a1, uint32_t a2, uint32_t a3,
    uint32_t b0, uint32_t b1)
{
    asm volatile(
        "mma.sync.aligned.m16n8k8.row.col.f32.tf32.tf32.f32 "
        "{%0,%1,%2,%3}, {%4,%5,%6,%7}, {%8,%9}, {%0,%1,%2,%3};"
        : "+f"(c0), "+f"(c1), "+f"(c2), "+f"(c3)
        : "r"(a0), "r"(a1), "r"(a2), "r"(a3), "r"(b0), "r"(b1));
}

// ---------------------------------------------------------------------------
// Pre-round fp32 -> tf32 bits (rna), vectorized. Writes device globals.
// which: 0 -> X into g_xtf, 1 -> W into g_wtf
// ---------------------------------------------------------------------------
__global__ __launch_bounds__(256) void preround_kernel(
    const float* __restrict__ in, int which, int n4)
{
    const int i = blockIdx.x * 256 + threadIdx.x;
    if (i < n4) {
        float* out = which ? g_wtf : g_xtf;
        float4 v = ((const float4*)in)[i];
        uint4 r = make_uint4(f2tf32(v.x), f2tf32(v.y), f2tf32(v.z), f2tf32(v.w));
        ((uint4*)out)[i] = r;
    }
}

// ---------------------------------------------------------------------------
// TF32 GEMM via mma.sync + cp.async double buffering.
// qkv[b,o,n] = sum_c W[o,c] * X[b,c,n]
// BM=128, BN=128, BK=16; 8 warps (2m x 4n), warp tile 64x32.
// SMEM: A stages [2][128][20] floats (pad 20 -> conflict-free frag LDS),
//       B stages [2][16][136] floats. Total 37888 B.
// ---------------------------------------------------------------------------
#define BK_     16
#define LDAP_   20      // A row stride (floats): 16 data + 4 pad
#define LDB_    136
#define A_ST    (128 * LDAP_ * 4)          // 10240 B per stage
#define B_ST    (16 * LDB_ * 4)            // 8704 B per stage
#define B_OFF   (2 * A_ST)                 // 20480
#define SM_TOT  (B_OFF + 2 * B_ST)         // 37888

__global__ __launch_bounds__(256) void gemm_qkv_tc()
{
    extern __shared__ uint8_t smem[];
    const uint32_t sbase = smem_u32(smem);
    float* const smf = (float*)smem;

    const int tid = threadIdx.x;
    const int bz  = blockIdx.z;
    const int bm0 = blockIdx.y * 128;
    const int bn0 = blockIdx.x * 128;

    const float* Ag = g_wtf + (size_t)bm0 * K_;               // [m][k] k-contig
    const float* Bg = g_xtf + (size_t)bz * C_ * HW_ + bn0;    // [k][n] n-contig
    float* Cg = g_qkv + ((size_t)bz * M_ + bm0) * HW_ + bn0;

    // cp.async chunk maps (2 A chunks + 2 B chunks per thread)
    const int ac0 = tid * 2;           // A chunk ids: ac0, ac0+1
    const int am0 = ac0 >> 2;          // A row of chunk 0 (chunks 4/row)
    const int aq0 = ac0 & 3;           // 16B quarter within row
    const int bc0 = tid * 2;           // B chunk ids (32 chunks/row)
    const int bk0 = bc0 >> 5;
    const int bq0 = bc0 & 31;

    // warp/fragment maps
    const int wid    = tid >> 5;
    const int lane   = tid & 31;
    const int warp_m = (wid & 1) * 64;
    const int warp_n = (wid >> 1) * 32;
    const int lr = lane >> 2;
    const int lc = lane & 3;

    float acc[4][4][4];
    #pragma unroll
    for (int mt = 0; mt < 4; mt++)
        #pragma unroll
        for (int nt = 0; nt < 4; nt++)
            #pragma unroll
            for (int r = 0; r < 4; r++) acc[mt][nt][r] = 0.f;

    // stage issue: stage s, k offset k0
    auto issue_stage = [&](int s, int k0) {
        {
            const int m = am0, q = aq0;
            uint32_t d0 = sbase + s * A_ST + (m * LDAP_ + q * 4) * 4;
            CP_ASYNC16(d0, Ag + (size_t)m * K_ + k0 + q * 4);
            const int c1 = ac0 + 1, m1 = c1 >> 2, q1 = c1 & 3;
            uint32_t d1 = sbase + s * A_ST + (m1 * LDAP_ + q1 * 4) * 4;
            CP_ASYNC16(d1, Ag + (size_t)m1 * K_ + k0 + q1 * 4);
        }
        {
            const int k = bk0, q = bq0;
            uint32_t d0 = sbase + B_OFF + s * B_ST + (k * LDB_ + q * 4) * 4;
            CP_ASYNC16(d0, Bg + (size_t)(k0 + k) * HW_ + q * 4);
            const int c1 = bc0 + 1, k1 = c1 >> 5, q1 = c1 & 31;
            uint32_t d1 = sbase + B_OFF + s * B_ST + (k1 * LDB_ + q1 * 4) * 4;
            CP_ASYNC16(d1, Bg + (size_t)(k0 + k1) * HW_ + q1 * 4);
        }
        CP_COMMIT();
    };

    // prologue: stages 0 and 1
    issue_stage(0, 0);
    issue_stage(1, BK_);

    const int NITER = K_ / BK_;   // 32
    for (int iter = 0; iter < NITER; iter++) {
        const int st = iter & 1;
        CP_WAIT1();            // stage `st` arrived (own-thread copies done)
        __syncthreads();       // publish to all threads

        const float* As = smf + st * (A_ST / 4);
        const float* Bs = smf + (B_OFF + st * B_ST) / 4;

        #pragma unroll
        for (int s = 0; s < 2; s++) {
            const int ks = s * 8;
            uint32_t af[4][4], bf[4][2];
            #pragma unroll
            for (int mt = 0; mt < 4; mt++) {
                const int r0 = warp_m + mt * 16 + lr;
                af[mt][0] = __float_as_uint(As[r0 * LDAP_ + ks + lc]);
                af[mt][1] = __float_as_uint(As[(r0 + 8) * LDAP_ + ks + lc]);
                af[mt][2] = __float_as_uint(As[r0 * LDAP_ + ks + lc + 4]);
                af[mt][3] = __float_as_uint(As[(r0 + 8) * LDAP_ + ks + lc + 4]);
            }
            #pragma unroll
            for (int nt = 0; nt < 4; nt++) {
                const int nb = warp_n + nt * 8 + lr;
                bf[nt][0] = __float_as_uint(Bs[(ks + lc) * LDB_ + nb]);
                bf[nt][1] = __float_as_uint(Bs[(ks + lc + 4) * LDB_ + nb]);
            }
            #pragma unroll
            for (int mt = 0; mt < 4; mt++)
                #pragma unroll
                for (int nt = 0; nt < 4; nt++)
                    mma_tf32(acc[mt][nt][0], acc[mt][nt][1],
                             acc[mt][nt][2], acc[mt][nt][3],
                             af[mt][0], af[mt][1], af[mt][2], af[mt][3],
                             bf[nt][0], bf[nt][1]);
        }

        __syncthreads();
        if (iter + 2 < NITER) issue_stage(st, (iter + 2) * BK_);
        else CP_COMMIT();   // keep wait_group counts consistent
    }

    // epilogue
    #pragma unroll
    for (int mt = 0; mt < 4; mt++) {
        const int r0 = warp_m + mt * 16 + lr;
        #pragma unroll
        for (int nt = 0; nt < 4; nt++) {
            const int cbase = warp_n + nt * 8 + 2 * lc;
            float2 v01 = make_float2(acc[mt][nt][0], acc[mt][nt][1]);
            float2 v23 = make_float2(acc[mt][nt][2], acc[mt][nt][3]);
            *(float2*)(Cg + (size_t)r0 * HW_ + cbase)       = v01;
            *(float2*)(Cg + (size_t)(r0 + 8) * HW_ + cbase) = v23;
        }
    }
}

// ---------------------------------------------------------------------------
// Global average pool
// ---------------------------------------------------------------------------
__global__ __launch_bounds__(256) void pool_kernel(const float* __restrict__ X)
{
    const int bc = blockIdx.x;
    const float* xp = X + (size_t)bc * HW_;
    float sum = 0.f;
    for (int i = threadIdx.x; i < HW_; i += 256) sum += xp[i];
    #pragma unroll
    for (int o = 16; o > 0; o >>= 1) sum += __shfl_xor_sync(0xFFFFFFFFu, sum, o);
    __shared__ float sm[8];
    if ((threadIdx.x & 31) == 0) sm[threadIdx.x >> 5] = sum;
    __syncthreads();
    if (threadIdx.x == 0) {
        float t = 0.f;
        #pragma unroll
        for (int i = 0; i < 8; i++) t += sm[i];
        g_pooled[bc] = t * (1.0f / HW_);
    }
}

// ---------------------------------------------------------------------------
// Gate softmax
// ---------------------------------------------------------------------------
__global__ void gate_kernel(const float* __restrict__ Wg, const float* __restrict__ bg)
{
    __shared__ float lg[32];
    const int t = threadIdx.x;
    const int b = t >> 2, i = t & 3;
    float dot = bg[i];
    const float* p = g_pooled + b * C_;
    const float* w = Wg + i * C_;
    for (int c = 0; c < C_; c++) dot += p[c] * w[c];
    lg[t] = dot;
    __syncthreads();
    if (t < B_) {
        float l0 = lg[t*4+0], l1 = lg[t*4+1], l2 = lg[t*4+2], l3 = lg[t*4+3];
        float m = fmaxf(fmaxf(l0, l1), fmaxf(l2, l3));
        float e0 = expf(l0 - m), e1 = expf(l1 - m), e2 = expf(l2 - m), e3 = expf(l3 - m);
        float inv = 1.0f / (e0 + e1 + e2 + e3);
        g_gate[t*4+0] = e0 * inv;
        g_gate[t*4+1] = e1 * inv;
        g_gate[t*4+2] = e2 * inv;
        g_gate[t*4+3] = e3 * inv;
    }
}

// ---------------------------------------------------------------------------
// Dilated 3x3 attention + gate + write out (zero-padding softmax semantics)
// ---------------------------------------------------------------------------
__global__ __launch_bounds__(256) void attn_kernel(float* __restrict__ out)
{
    const int n = blockIdx.x * 256 + threadIdx.x;
    const int dh = blockIdx.y;
    const int b  = blockIdx.z;
    const int i    = dh >> 1;
    const int head = dh & 1;
    const int dil  = 1 << i;
    const int h = n >> 6, w = n & 63;
    const float scale = 0.125f;

    const size_t base = ((size_t)b * M_ + i * 128 + head * 64) * HW_;
    const float* qp = g_qkv + base;
    const float* kp = g_qkv + base + (size_t)C_ * HW_;
    const float* vp = g_qkv + base + (size_t)2 * C_ * HW_;

    float s[9];
    int   nn[9];
    bool  ok[9];

    {
        float q[64];
        #pragma unroll
        for (int c = 0; c < 64; c++) q[c] = qp[(size_t)c * HW_ + n];

        #pragma unroll
        for (int j = 0; j < 9; j++) {
            const int dy = (j / 3 - 1) * dil;
            const int dx = (j % 3 - 1) * dil;
            const int hh = h + dy, ww = w + dx;
            const bool v_ok = ((unsigned)hh < 64u) && ((unsigned)ww < 64u);
            const int nnj = hh * 64 + ww;
            nn[j] = nnj; ok[j] = v_ok;
            float dot = 0.f;
            if (v_ok) {
                const float* kk = kp + nnj;
                #pragma unroll
                for (int c = 0; c < 64; c++) dot += q[c] * kk[(size_t)c * HW_];
            }
            s[j] = dot * scale;
        }
    }

    float m = s[0];
    #pragma unroll
    for (int j = 1; j < 9; j++) m = fmaxf(m, s[j]);
    float sum = 0.f;
    #pragma unroll
    for (int j = 0; j < 9; j++) { s[j] = expf(s[j] - m); sum += s[j]; }
    const float inv = 1.0f / sum;
    #pragma unroll
    for (int j = 0; j < 9; j++) s[j] *= inv;

    float acc[64];
    #pragma unroll
    for (int c = 0; c < 64; c++) acc[c] = 0.f;
    #pragma unroll
    for (int j = 0; j < 9; j++) {
        if (ok[j]) {
            const float p = s[j];
            const float* vv = vp + nn[j];
            #pragma unroll
            for (int c = 0; c < 64; c++) acc[c] += p * vv[(size_t)c * HW_];
        }
    }

    const float g = g_gate[b * 4 + i];
    float* op = out + ((size_t)b * C_ + i * 128 + head * 64) * HW_ + n;
    #pragma unroll
    for (int c = 0; c < 64; c++) op[(size_t)c * HW_] = g * acc[c];
}

// ---------------------------------------------------------------------------
extern "C" void kernel_launch(void* const* d_in, const int* in_sizes, int n_in,
                              void* d_out, int out_size)
{
    const float* x      = (const float*)d_in[0];
    const float* w_qkv  = (const float*)d_in[1];
    const float* w_gate = (const float*)d_in[2];
    const float* b_gate = (const float*)d_in[3];
    float* out = (float*)d_out;

    // pre-round inputs to tf32 (rna) once (writes g_xtf / g_wtf)
    preround_kernel<<<(B_ * C_ * HW_ / 4 + 255) / 256, 256>>>(x, 0, B_ * C_ * HW_ / 4);
    preround_kernel<<<(M_ * K_ / 4 + 255) / 256, 256>>>(w_qkv, 1, M_ * K_ / 4);

    // qkv GEMM (reads g_wtf/g_xtf, writes g_qkv)
    gemm_qkv_tc<<<dim3(HW_ / 128, M_ / 128, B_), 256, SM_TOT>>>();

    // gate path
    pool_kernel<<<B_ * C_, 256>>>(x);
    gate_kernel<<<1, 32>>>(w_gate, b_gate);

    // attention + gating + output
    attn_kernel<<<dim3(HW_ / 256, 8, B_), 256>>>(out);
}